// round 4
// baseline (speedup 1.0000x reference)
#include <cuda_runtime.h>
#include <cuda_bf16.h>

// LIF neuron: x_seq (T=64, B=32, F=8192) fp32 -> (spike_seq, mem_seq) each (T,B,F).
// R3 -> R4: float2 per thread instead of float4 -> 131072 threads
// (28 warps/SM, 2x occupancy). Read-MLP was already sufficient (PF=8 ring);
// the exposed stalls were warp-count-limited (occ 19.5%, issue 11.5%, no pipe
// saturated). Same total bytes-in-flight, double the warps to cover them.

static constexpr int T  = 64;
static constexpr int BF = 32 * 8192;      // 262144 lanes
static constexpr int N2 = BF / 2;         // 131072 float2 lanes
static constexpr int PF = 8;              // outstanding LDG.64 per thread

__global__ __launch_bounds__(128) void lif_kernel(
    const float2* __restrict__ x,     // [T, N2]
    float*        __restrict__ out)   // [2, T, N2*2] : spike then mem
{
    const int lane = blockIdx.x * 128 + threadIdx.x;

    float2* spike_out = reinterpret_cast<float2*>(out);
    float2* mem_out   = reinterpret_cast<float2*>(out) + (size_t)T * N2;

    // Prime the prefetch ring: 8 LDG.64 in flight before any compute.
    float2 buf[PF];
    #pragma unroll
    for (int i = 0; i < PF; i++)
        buf[i] = __ldcg(&x[(size_t)i * N2 + lane]);

    float mx = 0.0f, my = 0.0f;

    #pragma unroll
    for (int t = 0; t < T; t++) {
        const float2 xv = buf[t & (PF - 1)];

        if (t + PF < T)
            buf[t & (PF - 1)] = __ldcg(&x[(size_t)(t + PF) * N2 + lane]);

        // mem = mem*0.5 + x   (*0.5 is exact, fma == mul+add bitwise)
        mx = __fmaf_rn(mx, 0.5f, xv.x);
        my = __fmaf_rn(my, 0.5f, xv.y);

        float2 s;
        s.x = (mx >= 1.0f) ? 1.0f : 0.0f;
        s.y = (my >= 1.0f) ? 1.0f : 0.0f;

        // reset: mem = 0 where spiked (V_RESET = 0)
        mx = (s.x != 0.0f) ? 0.0f : mx;
        my = (s.y != 0.0f) ? 0.0f : my;

        const float2 m = {mx, my};

        __stcs(&spike_out[(size_t)t * N2 + lane], s);
        __stcs(&mem_out  [(size_t)t * N2 + lane], m);
    }
}

extern "C" void kernel_launch(void* const* d_in, const int* in_sizes, int n_in,
                              void* d_out, int out_size) {
    const float2* x = reinterpret_cast<const float2*>(d_in[0]);
    float* out = reinterpret_cast<float*>(d_out);

    const int threads = 128;
    const int blocks  = N2 / threads;   // 1024 blocks
    lif_kernel<<<blocks, threads>>>(x, out);
}

// round 6
// speedup vs baseline: 1.0562x; 1.0562x over previous
#include <cuda_runtime.h>
#include <cuda_bf16.h>

// LIF neuron: x_seq (T=64, B=32, F=8192) fp32 -> (spike_seq, mem_seq) each (T,B,F).
// R5 -> R6: same L2-residency theory (out = 128 MiB ~fits the 126 MB L2 and is
// overwritten every graph replay -> keep it resident; x = 64 MiB streams
// through evict-first). sm_103 only accepts the literal .L2::evict_last
// qualifier on 256-bit stores, so use the general form: createpolicy +
// L2::cache_hint on both ld and st.

static constexpr int T  = 64;
static constexpr int BF = 32 * 8192;      // 262144 lanes
static constexpr int N4 = BF / 4;         // 65536 float4 lanes
static constexpr int PF = 8;              // outstanding LDG.128 per thread

__device__ __forceinline__ unsigned long long make_policy_evict_last() {
    unsigned long long pol;
    asm("createpolicy.fractional.L2::evict_last.b64 %0, 1.0;" : "=l"(pol));
    return pol;
}

__device__ __forceinline__ unsigned long long make_policy_evict_first() {
    unsigned long long pol;
    asm("createpolicy.fractional.L2::evict_first.b64 %0, 1.0;" : "=l"(pol));
    return pol;
}

__device__ __forceinline__ float4 ldg_hint(const float4* p, unsigned long long pol) {
    float4 v;
    asm volatile("ld.global.nc.L2::cache_hint.v4.f32 {%0,%1,%2,%3}, [%4], %5;"
                 : "=f"(v.x), "=f"(v.y), "=f"(v.z), "=f"(v.w)
                 : "l"(p), "l"(pol));
    return v;
}

__device__ __forceinline__ void stg_hint(float4* p, float4 v, unsigned long long pol) {
    asm volatile("st.global.L2::cache_hint.v4.f32 [%0], {%1,%2,%3,%4}, %5;"
                 :: "l"(p), "f"(v.x), "f"(v.y), "f"(v.z), "f"(v.w), "l"(pol)
                 : "memory");
}

__global__ __launch_bounds__(64) void lif_kernel(
    const float4* __restrict__ x,     // [T, N4]
    float*        __restrict__ out)   // [2, T, N4*4] : spike then mem
{
    const int lane = blockIdx.x * 64 + threadIdx.x;

    const unsigned long long pol_ld = make_policy_evict_first();
    const unsigned long long pol_st = make_policy_evict_last();

    float4* spike_out = reinterpret_cast<float4*>(out);
    float4* mem_out   = reinterpret_cast<float4*>(out) + (size_t)T * N4;

    // Prime the prefetch ring: 8 LDG.128 in flight before any compute.
    float4 buf[PF];
    #pragma unroll
    for (int i = 0; i < PF; i++)
        buf[i] = ldg_hint(&x[(size_t)i * N4 + lane], pol_ld);

    float mx = 0.0f, my = 0.0f, mz = 0.0f, mw = 0.0f;

    #pragma unroll
    for (int t = 0; t < T; t++) {
        const float4 xv = buf[t & (PF - 1)];

        if (t + PF < T)
            buf[t & (PF - 1)] = ldg_hint(&x[(size_t)(t + PF) * N4 + lane], pol_ld);

        // mem = mem*0.5 + x   (*0.5 is exact, fma == mul+add bitwise)
        mx = __fmaf_rn(mx, 0.5f, xv.x);
        my = __fmaf_rn(my, 0.5f, xv.y);
        mz = __fmaf_rn(mz, 0.5f, xv.z);
        mw = __fmaf_rn(mw, 0.5f, xv.w);

        float4 s;
        s.x = (mx >= 1.0f) ? 1.0f : 0.0f;
        s.y = (my >= 1.0f) ? 1.0f : 0.0f;
        s.z = (mz >= 1.0f) ? 1.0f : 0.0f;
        s.w = (mw >= 1.0f) ? 1.0f : 0.0f;

        // reset: mem = 0 where spiked (V_RESET = 0)
        mx = (s.x != 0.0f) ? 0.0f : mx;
        my = (s.y != 0.0f) ? 0.0f : my;
        mz = (s.z != 0.0f) ? 0.0f : mz;
        mw = (s.w != 0.0f) ? 0.0f : mw;

        const float4 m = {mx, my, mz, mw};

        stg_hint(&spike_out[(size_t)t * N4 + lane], s, pol_st);
        stg_hint(&mem_out  [(size_t)t * N4 + lane], m, pol_st);
    }
}

extern "C" void kernel_launch(void* const* d_in, const int* in_sizes, int n_in,
                              void* d_out, int out_size) {
    const float4* x = reinterpret_cast<const float4*>(d_in[0]);
    float* out = reinterpret_cast<float*>(d_out);

    const int threads = 64;
    const int blocks  = N4 / threads;   // 1024 blocks
    lif_kernel<<<blocks, threads>>>(x, out);
}